// round 5
// baseline (speedup 1.0000x reference)
#include <cuda_runtime.h>
#include <math.h>

// Problem constants
#define N_NODES 102400
#define N_EDGES 819200
#define N_GRAPH 512
#define NPG     200
#define BB      8
#define TT      64
#define DD      128
#define NH      4
#define DH      32
#define NL      4
#define HID     64

// ---------------- scratch (device globals; no allocation) ----------------
__device__ __align__(256) int   g_indeg [N_NODES];
__device__ __align__(256) int   g_cursor[N_NODES];
__device__ __align__(256) int   g_rowp  [N_NODES + 1];
__device__ __align__(256) int   g_gtot  [N_GRAPH];
__device__ __align__(256) int   g_gbase [N_GRAPH];
__device__ __align__(256) int   g_ecol  [N_EDGES];
__device__ __align__(256) float g_dinv  [N_NODES];
__device__ __align__(256) float g_wt    [N_NODES];
__device__ __align__(256) float g_x1    [N_NODES * 2];
__device__ __align__(256) float g_h     [N_NODES * HID];
__device__ __align__(256) float g_agg   [N_NODES * HID];
__device__ __align__(256) float g_seq [BB * TT * DD];
__device__ __align__(256) float g_qkv [BB * TT * 3 * DD];
__device__ __align__(256) float g_att [BB * TT * DD];
__device__ __align__(256) float g_ffn [BB * TT * 4 * DD];

// ---------------- software grid barrier ----------------
__device__ unsigned int bar_cnt = 0;
__device__ volatile unsigned int bar_gen = 0;

__device__ __forceinline__ void gsync() {
    __syncthreads();
    if (threadIdx.x == 0) {
        __threadfence();                       // release my block's writes
        unsigned int g = bar_gen;
        if (atomicAdd(&bar_cnt, 1u) == gridDim.x - 1u) {
            atomicExch(&bar_cnt, 0u);
            __threadfence();
            bar_gen = g + 1u;
        } else {
            while (bar_gen == g) { __nanosleep(64); }
        }
        __threadfence();                       // acquire
    }
    __syncthreads();
}

// ---------------- device helpers ----------------
// 64x64-tile GEMM: C = A(MxK) @ B(NxK)^T + bias, opt relu. 256 threads.
__device__ void gemm64_tile(const float* __restrict__ A, const float* __restrict__ B,
                            const float* __restrict__ bias, float* __restrict__ C,
                            int N, int K, int relu, int m0, int n0, float* sp) {
    float (*As)[17] = (float(*)[17])sp;
    float (*Bs)[17] = (float(*)[17])(sp + 1088);
    int tid = threadIdx.x;
    int tx = tid & 15, ty = tid >> 4;
    float acc[4][4] = {};
    for (int k0 = 0; k0 < K; k0 += 16) {
        #pragma unroll
        for (int i = 0; i < 4; i++) {
            int idx = tid + i * 256;
            int r = idx >> 4, c = idx & 15;
            As[r][c] = __ldcg(&A[(m0 + r) * K + k0 + c]);
            Bs[r][c] = B[(n0 + r) * K + k0 + c];
        }
        __syncthreads();
        #pragma unroll
        for (int kk = 0; kk < 16; kk++) {
            float a[4], bb[4];
            #pragma unroll
            for (int i = 0; i < 4; i++) a[i]  = As[ty * 4 + i][kk];
            #pragma unroll
            for (int j = 0; j < 4; j++) bb[j] = Bs[tx * 4 + j][kk];
            #pragma unroll
            for (int i = 0; i < 4; i++)
                #pragma unroll
                for (int j = 0; j < 4; j++) acc[i][j] += a[i] * bb[j];
        }
        __syncthreads();
    }
    #pragma unroll
    for (int i = 0; i < 4; i++)
        #pragma unroll
        for (int j = 0; j < 4; j++) {
            float v = acc[i][j] + bias[n0 + tx * 4 + j];
            if (relu) v = fmaxf(v, 0.f);
            C[(m0 + ty * 4 + i) * N + n0 + tx * 4 + j] = v;
        }
    __syncthreads();
}

// 8-row GEMM + residual + LN into seq. N=128 outputs. K multiple of 64. 256 threads.
__device__ void gemm_ln8(const float* __restrict__ A, const float* __restrict__ W,
                         const float* __restrict__ bias, const float* __restrict__ gam,
                         const float* __restrict__ bet, float* __restrict__ seq,
                         int K, int r0, float* sp) {
    float* Wt  = sp;            // 128 x 66
    float* Ar  = sp + 8448;     // 8 x 66
    float* red = sp + 8976;     // 64
    int tid = threadIdx.x;
    int col = tid & 127, rg = tid >> 7;     // rg 0/1: rows rg*4..+3
    int lane = tid & 31;
    float acc[4] = {0.f, 0.f, 0.f, 0.f};
    int nch = K >> 6;
    for (int ch = 0; ch < nch; ch++) {
        for (int idx = tid; idx < 128 * 64; idx += 256) {
            int r = idx >> 6, kk = idx & 63;
            Wt[r * 66 + kk] = W[r * K + ch * 64 + kk];
        }
        for (int idx = tid; idx < 8 * 64; idx += 256) {
            int r = idx >> 6, kk = idx & 63;
            Ar[r * 66 + kk] = __ldcg(&A[(r0 + r) * K + ch * 64 + kk]);
        }
        __syncthreads();
        const float2* Wc = (const float2*)(Wt + col * 66);
        #pragma unroll 8
        for (int k2 = 0; k2 < 32; k2++) {
            float2 w = Wc[k2];
            #pragma unroll
            for (int i = 0; i < 4; i++) {
                float2 a = ((const float2*)(Ar + (rg * 4 + i) * 66))[k2];
                acc[i] += a.x * w.x + a.y * w.y;
            }
        }
        __syncthreads();
    }
    float bcol = bias[col], gcol = gam[col], becol = bet[col];
    float v[4], s[4], q[4];
    #pragma unroll
    for (int i = 0; i < 4; i++) {
        int r = r0 + rg * 4 + i;
        v[i] = acc[i] + bcol + __ldcg(&seq[r * 128 + col]);
        s[i] = v[i]; q[i] = v[i] * v[i];
    }
    #pragma unroll
    for (int o = 16; o; o >>= 1) {
        #pragma unroll
        for (int i = 0; i < 4; i++) {
            s[i] += __shfl_xor_sync(0xffffffffu, s[i], o);
            q[i] += __shfl_xor_sync(0xffffffffu, q[i], o);
        }
    }
    int wid = tid >> 5;
    if (lane == 0) {
        #pragma unroll
        for (int i = 0; i < 4; i++) { red[wid * 8 + i] = s[i]; red[wid * 8 + 4 + i] = q[i]; }
    }
    __syncthreads();
    #pragma unroll
    for (int i = 0; i < 4; i++) {
        int wb = rg * 4;
        float S = red[wb * 8 + i] + red[(wb + 1) * 8 + i] + red[(wb + 2) * 8 + i] + red[(wb + 3) * 8 + i];
        float Q = red[wb * 8 + 4 + i] + red[(wb + 1) * 8 + 4 + i] + red[(wb + 2) * 8 + 4 + i] + red[(wb + 3) * 8 + 4 + i];
        float m  = S * (1.f / 128.f);
        float iv = rsqrtf(Q * (1.f / 128.f) - m * m + 1e-5f);
        seq[(r0 + rg * 4 + i) * 128 + col] = (v[i] - m) * iv * gcol + becol;
    }
    __syncthreads();
}

// =============== the mono-kernel ===============
__global__ void __launch_bounds__(256, 2) k_mono(
    const float* __restrict__ x,
    const int* __restrict__ esrc, const int* __restrict__ edst,
    const float* __restrict__ W1, const float* __restrict__ b1,
    const float* __restrict__ g1, const float* __restrict__ be1,
    const float* __restrict__ W2, const float* __restrict__ b2,
    const float* __restrict__ g2, const float* __restrict__ be2,
    const float* __restrict__ W3, const float* __restrict__ b3,
    const float* __restrict__ tWqkv, const float* __restrict__ tbqkv,
    const float* __restrict__ tWo,  const float* __restrict__ tbo,
    const float* __restrict__ tg1,  const float* __restrict__ tb1,
    const float* __restrict__ tg2,  const float* __restrict__ tb2,
    const float* __restrict__ tWf1, const float* __restrict__ tbf1,
    const float* __restrict__ tWf2, const float* __restrict__ tbf2,
    const float* __restrict__ hW1,  const float* __restrict__ hb1,
    const float* __restrict__ hW2,  const float* __restrict__ hb2,
    float* __restrict__ out)
{
    __shared__ __align__(16) float sp[10496];
    int tid  = threadIdx.x;
    int gtid = blockIdx.x * 256 + tid;
    int GT   = gridDim.x * 256;
    int lane = tid & 31;

    // ---- P0: zero histogram/cursor ----
    for (int i = gtid; i < N_NODES; i += GT) { g_indeg[i] = 0; g_cursor[i] = 0; }
    gsync();

    // ---- P1: in-degree histogram ----
    for (int e = gtid; e < N_EDGES; e += GT) atomicAdd(&g_indeg[edst[e]], 1);
    gsync();

    // ---- P2: per-graph scan + node prep (dinv, wt init, prescaled x) ----
    {
        int* ib0 = (int*)sp; int* ib1 = ib0 + 256;
        for (int g = blockIdx.x; g < N_GRAPH; g += gridDim.x) {
            int n = g * NPG + tid;
            int v = 0;
            if (tid < NPG) {
                v = __ldcg(&g_indeg[n]);
                float di = rsqrtf((float)(v + 1));
                g_dinv[n] = di;
                g_wt[n]   = di * di;
                float2 xv = *(const float2*)&x[2 * n];
                xv.x *= di; xv.y *= di;
                ((float2*)g_x1)[n] = xv;
            }
            int* a = ib0; int* b = ib1;
            a[tid] = v; __syncthreads();
            #pragma unroll
            for (int o = 1; o < 256; o <<= 1) {
                int xv2 = a[tid];
                if (tid >= o) xv2 += a[tid - o];
                b[tid] = xv2; __syncthreads();
                int* t = a; a = b; b = t;
            }
            if (tid < NPG) g_rowp[n] = a[tid] - v;
            if (tid == NPG - 1) g_gtot[g] = a[tid];
            __syncthreads();
        }
    }
    gsync();

    // ---- P3: scan graph totals (block 0) ----
    if (blockIdx.x == 0) {
        int* ib0 = (int*)sp; int* ib1 = ib0 + 256;
        int e0 = __ldcg(&g_gtot[2 * tid]);
        int e1 = __ldcg(&g_gtot[2 * tid + 1]);
        int pair = e0 + e1;
        int* a = ib0; int* b = ib1;
        a[tid] = pair; __syncthreads();
        #pragma unroll
        for (int o = 1; o < 256; o <<= 1) {
            int xv2 = a[tid];
            if (tid >= o) xv2 += a[tid - o];
            b[tid] = xv2; __syncthreads();
            int* t = a; a = b; b = t;
        }
        int excl = a[tid] - pair;
        g_gbase[2 * tid]     = excl;
        g_gbase[2 * tid + 1] = excl + e0;
    }
    gsync();

    // ---- P4: globalize row pointers ----
    for (int i = gtid; i < N_NODES; i += GT)
        g_rowp[i] = __ldcg(&g_rowp[i]) + __ldcg(&g_gbase[i / NPG]);
    if (gtid == 0) g_rowp[N_NODES] = N_EDGES;
    gsync();

    // ---- P5: scatter edges into CSR + layer-3 fold weights ----
    for (int e = gtid; e < N_EDGES; e += GT) {
        int s = esrc[e], d = edst[e];
        int pos = __ldcg(&g_rowp[d]) + atomicAdd(&g_cursor[d], 1);
        g_ecol[pos] = s;
        atomicAdd(&g_wt[s], __ldcg(&g_dinv[s]) * __ldcg(&g_dinv[d]));
    }
    gsync();

    // ---- P6: layer-1 aggregate + transform + LN (warp per node) ----
    {
        int j = 2 * lane;
        float w00 = W1[j], w01 = W1[64 + j], w10 = W1[j + 1], w11 = W1[65 + j];
        float bb0 = b1[j], bb1 = b1[j + 1];
        float gg0 = g1[j], gg1 = g1[j + 1];
        float e0v = be1[j], e1v = be1[j + 1];
        int wtot = GT >> 5;
        int gw = gtid >> 5;
        const float2* x2 = (const float2*)g_x1;
        float2* h2 = (float2*)g_h;
        for (int n = gw; n < N_NODES; n += wtot) {
            int r0 = __ldcg(&g_rowp[n]), r1 = __ldcg(&g_rowp[n + 1]);
            float a0 = 0.f, a1 = 0.f;
            if (lane == 0) { float2 sv = __ldcg(&x2[n]); a0 = sv.x; a1 = sv.y; }
            for (int e = r0 + lane; e < r1; e += 32) {
                int c = __ldcg(&g_ecol[e]);
                float2 v = __ldcg(&x2[c]);
                a0 += v.x; a1 += v.y;
            }
            #pragma unroll
            for (int o = 16; o; o >>= 1) {
                a0 += __shfl_xor_sync(0xffffffffu, a0, o);
                a1 += __shfl_xor_sync(0xffffffffu, a1, o);
            }
            float di = __ldcg(&g_dinv[n]);
            a0 *= di; a1 *= di;
            float v0 = fmaxf(a0 * w00 + a1 * w01 + bb0, 0.f);
            float v1 = fmaxf(a0 * w10 + a1 * w11 + bb1, 0.f);
            float s = v0 + v1, q = v0 * v0 + v1 * v1;
            #pragma unroll
            for (int o = 16; o; o >>= 1) {
                s += __shfl_xor_sync(0xffffffffu, s, o);
                q += __shfl_xor_sync(0xffffffffu, q, o);
            }
            float m  = s * (1.f / 64.f);
            float iv = rsqrtf(q * (1.f / 64.f) - m * m + 1e-5f);
            float h0 = ((v0 - m) * iv * gg0 + e0v) * di;
            float h1 = ((v1 - m) * iv * gg1 + e1v) * di;
            h2[n * 32 + lane] = make_float2(h0, h1);
        }
    }
    gsync();

    // ---- P7: layer-2 aggregate (warp per node, gather) ----
    {
        int wtot = GT >> 5;
        int gw = gtid >> 5;
        const float2* h2 = (const float2*)g_h;
        float2* ag2 = (float2*)g_agg;
        for (int n = gw; n < N_NODES; n += wtot) {
            float2 acc = __ldcg(&h2[n * 32 + lane]);     // self (prescaled)
            int r0 = __ldcg(&g_rowp[n]), r1 = __ldcg(&g_rowp[n + 1]);
            int e = r0;
            for (; e + 1 < r1; e += 2) {
                int c0 = __ldcg(&g_ecol[e]), c1 = __ldcg(&g_ecol[e + 1]);
                float2 v0 = __ldcg(&h2[c0 * 32 + lane]);
                float2 v1 = __ldcg(&h2[c1 * 32 + lane]);
                acc.x += v0.x + v1.x; acc.y += v0.y + v1.y;
            }
            if (e < r1) {
                int c = __ldcg(&g_ecol[e]);
                float2 v = __ldcg(&h2[c * 32 + lane]);
                acc.x += v.x; acc.y += v.y;
            }
            float di = __ldcg(&g_dinv[n]);
            acc.x *= di; acc.y *= di;
            ag2[n * 32 + lane] = acc;
        }
    }
    gsync();

    // ---- P8: layer-2 transform + LN ----
    {
        float* sW2  = sp;            // 4096
        float* rows = sp + 4096;     // 1024
        float* bs   = sp + 5120;
        float* gs   = sp + 5184;
        float* bes  = sp + 5248;
        for (int i = tid; i < 4096; i += 256) sW2[i] = W2[i];
        if (tid < 64) { bs[tid] = b2[tid]; gs[tid] = g2[tid]; bes[tid] = be2[tid]; }
        __syncthreads();
        const float4* Ws = (const float4*)sW2;
        int slot = tid >> 4, jg = tid & 15;
        for (int t = blockIdx.x; t < N_NODES / 16; t += gridDim.x) {
            int base = t * 16 * 64;
            for (int i = tid; i < 1024; i += 256) rows[i] = __ldcg(&g_agg[base + i]);
            __syncthreads();
            const float* r = &rows[slot * 64];
            float a0 = 0, a1 = 0, a2 = 0, a3 = 0;
            #pragma unroll
            for (int k = 0; k < 64; k++) {
                float rv = r[k];
                float4 w = Ws[k * 16 + jg];
                a0 += rv * w.x; a1 += rv * w.y; a2 += rv * w.z; a3 += rv * w.w;
            }
            int j0 = jg * 4;
            float v0 = fmaxf(a0 + bs[j0],     0.f);
            float v1 = fmaxf(a1 + bs[j0 + 1], 0.f);
            float v2 = fmaxf(a2 + bs[j0 + 2], 0.f);
            float v3 = fmaxf(a3 + bs[j0 + 3], 0.f);
            float s = v0 + v1 + v2 + v3;
            float q = v0 * v0 + v1 * v1 + v2 * v2 + v3 * v3;
            #pragma unroll
            for (int o = 8; o; o >>= 1) {
                s += __shfl_xor_sync(0xffffffffu, s, o);
                q += __shfl_xor_sync(0xffffffffu, q, o);
            }
            float m  = s * (1.f / 64.f);
            float iv = rsqrtf(q * (1.f / 64.f) - m * m + 1e-5f);
            float4 o4;
            o4.x = (v0 - m) * iv * gs[j0]     + bes[j0];
            o4.y = (v1 - m) * iv * gs[j0 + 1] + bes[j0 + 1];
            o4.z = (v2 - m) * iv * gs[j0 + 2] + bes[j0 + 2];
            o4.w = (v3 - m) * iv * gs[j0 + 3] + bes[j0 + 3];
            ((float4*)g_h)[(t * 16 + slot) * 16 + jg] = o4;
            __syncthreads();
        }
    }
    gsync();

    // ---- P9: readout (layer-3 folded) + PE ----
    {
        float* wts  = sp;
        float* part = sp + 256;
        float* am   = sp + 512;
        for (int g = blockIdx.x; g < N_GRAPH; g += gridDim.x) {
            for (int i = tid; i < NPG; i += 256) wts[i] = __ldcg(&g_wt[g * NPG + i]);
            __syncthreads();
            int j = tid & 63, qtr = tid >> 6;
            const float* basep = &g_h[(g * NPG + qtr * 50) * 64];
            const float* wb = &wts[qtr * 50];
            float s = 0.f;
            for (int nn = 0; nn < 50; nn++) s += wb[nn] * __ldcg(&basep[nn * 64 + j]);
            part[tid] = s;
            __syncthreads();
            if (tid < 64)
                am[tid] = (part[tid] + part[64 + tid] + part[128 + tid] + part[192 + tid]) * (1.f / 200.f);
            __syncthreads();
            if (tid < 128) {
                float acc = b3[tid];
                #pragma unroll
                for (int k = 0; k < 64; k++) acc += am[k] * W3[k * 128 + tid];
                int ts = g & 63;
                int i2 = tid >> 1;
                float dv  = expf((float)(2 * i2) * (-9.210340371976184f / 128.0f));
                float ang = (float)ts * dv;
                float pe  = (tid & 1) ? cosf(ang) : sinf(ang);
                g_seq[g * 128 + tid] = acc + pe;
            }
            __syncthreads();
        }
    }
    gsync();

    // ---- transformer layers ----
    for (int l = 0; l < NL; l++) {
        // qkv GEMM: 512x384, K=128 -> 48 tiles
        for (int t = blockIdx.x; t < 48; t += gridDim.x)
            gemm64_tile(g_seq, tWqkv + l * 384 * 128, tbqkv + l * 384, g_qkv,
                        384, 128, 0, (t / 6) * 64, (t % 6) * 64, sp);
        gsync();

        // attention: 32 (b,h) blocks
        {
            float* qs  = sp;
            float* ks  = sp + 2048;
            float* vs  = sp + 4096;
            float* ssm = sp + 6144;    // 64 x 65
            for (int bh = blockIdx.x; bh < 32; bh += gridDim.x) {
                int b = bh >> 2, h = bh & 3;
                for (int idx = tid; idx < 2048; idx += 256) {
                    int tok = idx >> 5, d = idx & 31;
                    const float* row = &g_qkv[(b * 64 + tok) * 384 + h * 32 + d];
                    qs[idx] = __ldcg(row);
                    ks[idx] = __ldcg(row + 128);
                    vs[idx] = __ldcg(row + 256);
                }
                __syncthreads();
                int tok = tid & 63, q4 = tid >> 6;
                for (int j = q4 * 16; j < q4 * 16 + 16; j++) {
                    float a = 0.f;
                    #pragma unroll
                    for (int d = 0; d < 32; d++) a += qs[tok * 32 + d] * ks[j * 32 + d];
                    ssm[tok * 65 + j] = a * 0.17677669529663687f;
                }
                __syncthreads();
                float mx = -1e30f;
                #pragma unroll 8
                for (int j = 0; j < 64; j++) mx = fmaxf(mx, ssm[tok * 65 + j]);
                __syncthreads();
                if (q4 == 0) {
                    for (int j = 0; j < 64; j++)
                        ssm[tok * 65 + j] = __expf(ssm[tok * 65 + j] - mx);
                }
                __syncthreads();
                float sum = 0.f;
                #pragma unroll 8
                for (int j = 0; j < 64; j++) sum += ssm[tok * 65 + j];
                float inv = 1.0f / sum;
                for (int d = q4 * 8; d < q4 * 8 + 8; d++) {
                    float o = 0.f;
                    #pragma unroll 8
                    for (int j = 0; j < 64; j++) o += ssm[tok * 65 + j] * vs[j * 32 + d];
                    g_att[(b * 64 + tok) * 128 + h * 32 + d] = o * inv;
                }
                __syncthreads();
            }
        }
        gsync();

        // o-proj + residual + LN: 64 row-tiles of 8
        for (int t = blockIdx.x; t < 64; t += gridDim.x)
            gemm_ln8(g_att, tWo + l * 128 * 128, tbo + l * 128,
                     tg1 + l * 128, tb1 + l * 128, g_seq, 128, t * 8, sp);
        gsync();

        // ffn1 (relu): 512x512, K=128 -> 64 tiles
        for (int t = blockIdx.x; t < 64; t += gridDim.x)
            gemm64_tile(g_seq, tWf1 + l * 512 * 128, tbf1 + l * 512, g_ffn,
                        512, 128, 1, (t >> 3) * 64, (t & 7) * 64, sp);
        gsync();

        // ffn2 + residual + LN: K=512 -> 64 row-tiles of 8
        for (int t = blockIdx.x; t < 64; t += gridDim.x)
            gemm_ln8(g_ffn, tWf2 + l * 128 * 512, tbf2 + l * 128,
                     tg2 + l * 128, tb2 + l * 128, g_seq, 512, t * 8, sp);
        gsync();
    }

    // ---- head ----
    if (blockIdx.x < BB) {
        int b = blockIdx.x;
        float* p  = sp;
        float* hh = sp + 128;
        if (tid < 128) {
            float s = 0.f;
            for (int t = 0; t < 64; t++) s += __ldcg(&g_seq[(b * 64 + t) * 128 + tid]);
            p[tid] = s * (1.0f / 64.0f);
        }
        __syncthreads();
        if (tid < 64) {
            float a = hb1[tid];
            #pragma unroll
            for (int k = 0; k < 128; k++) a += p[k] * hW1[tid * 128 + k];
            hh[tid] = fmaxf(a, 0.f);
        }
        __syncthreads();
        if (tid < 2) {
            float o = hb2[tid];
            #pragma unroll
            for (int k = 0; k < 64; k++) o += hh[k] * hW2[tid * 64 + k];
            out[b * 2 + tid] = o;
        }
    }
}

// =============== host launcher: ONE kernel ===============
extern "C" void kernel_launch(void* const* d_in, const int* in_sizes, int n_in,
                              void* d_out, int out_size) {
    const float* x     = (const float*)d_in[0];
    const int*   esrc  = (const int*)d_in[1];
    const int*   edst  = (const int*)d_in[2];
    const float* gW1   = (const float*)d_in[4];
    const float* gb1   = (const float*)d_in[5];
    const float* ln1g  = (const float*)d_in[6];
    const float* ln1b  = (const float*)d_in[7];
    const float* gW2   = (const float*)d_in[8];
    const float* gb2   = (const float*)d_in[9];
    const float* ln2g  = (const float*)d_in[10];
    const float* ln2b  = (const float*)d_in[11];
    const float* gW3   = (const float*)d_in[12];
    const float* gb3   = (const float*)d_in[13];
    const float* tWqkv = (const float*)d_in[14];
    const float* tbqkv = (const float*)d_in[15];
    const float* tWo   = (const float*)d_in[16];
    const float* tbo   = (const float*)d_in[17];
    const float* tg1   = (const float*)d_in[18];
    const float* tb1   = (const float*)d_in[19];
    const float* tg2   = (const float*)d_in[20];
    const float* tb2   = (const float*)d_in[21];
    const float* tWf1  = (const float*)d_in[22];
    const float* tbf1  = (const float*)d_in[23];
    const float* tWf2  = (const float*)d_in[24];
    const float* tbf2  = (const float*)d_in[25];
    const float* hW1   = (const float*)d_in[26];
    const float* hb1   = (const float*)d_in[27];
    const float* hW2   = (const float*)d_in[28];
    const float* hb2   = (const float*)d_in[29];

    int sms = 148;
    cudaDeviceGetAttribute(&sms, cudaDevAttrMultiProcessorCount, 0);

    k_mono<<<sms, 256>>>(x, esrc, edst,
                         gW1, gb1, ln1g, ln1b,
                         gW2, gb2, ln2g, ln2b,
                         gW3, gb3,
                         tWqkv, tbqkv, tWo, tbo,
                         tg1, tb1, tg2, tb2,
                         tWf1, tbf1, tWf2, tbf2,
                         hW1, hb1, hW2, hb2,
                         (float*)d_out);
}